// round 3
// baseline (speedup 1.0000x reference)
#include <cuda_runtime.h>
#include <math.h>

#define BQ    8
#define SEQ   512
#define NVAR  1024
#define TFEAT 7
#define LTOK  1031           // NVAR + TFEAT
#define MTOT  8248           // BQ * LTOK
#define DMOD  128
#define DST   16
#define PREDN 96

// ---------------- scratch (device globals; no allocation allowed) ----------------
__device__ float g_tok[MTOT * SEQ];          // masked, transposed tokens [m][s]
__device__ float g_h  [MTOT * DMOD];
__device__ float g_ln1[MTOT * DMOD];
__device__ float g_ffn[MTOT * DMOD];
__device__ float g_xz [MTOT * 512];          // [m][0:128 xr_f |128:256 z_f |256:384 xr_r |384:512 z_r]
__device__ float g_xc [2 * MTOT * DMOD];     // per dir, scan-time order
__device__ float g_dbc[2 * MTOT * 160];      // per dir: delta(128) B(16) C(16), scan-time order
__device__ float g_y  [MTOT * 256];          // scan output, ORIGINAL order, [m][dir*128+d]
__device__ float g_po [MTOT * PREDN];
__device__ float g_wxp[4 * 160 * DMOD];      // per (l,dir): rows0-127 = dpw@xpw[:8]; 128-159 = xpw[8:40]
__device__ float g_wop[2 * DMOD * 256];      // per l: out_proj concat over dirs along K

// ---------------- token transpose + mask: x_enc[b][s][v] -> tok[b*LTOK+v][s] -----
__global__ void tok_prep(const float* __restrict__ x_enc, float* __restrict__ tok)
{
    __shared__ float tile[32][33];
    int b = blockIdx.z;
    int s0 = blockIdx.x * 32, v0 = blockIdx.y * 32;
    #pragma unroll
    for (int i = 0; i < 4; i++) {
        int s = s0 + threadIdx.y + i * 8;
        float x = x_enc[((size_t)(b * SEQ + s)) * NVAR + v0 + threadIdx.x];
        tile[threadIdx.y + i * 8][threadIdx.x] = (x == -9999.0f) ? -1.0f : x;
    }
    __syncthreads();
    #pragma unroll
    for (int i = 0; i < 4; i++) {
        int v = v0 + threadIdx.y + i * 8;
        tok[((size_t)(b * LTOK + v)) * SEQ + s0 + threadIdx.x] = tile[threadIdx.x][threadIdx.y + i * 8];
    }
}

__global__ void mark_prep(const float* __restrict__ x_mark, float* __restrict__ tok)
{
    int idx = blockIdx.x * 256 + threadIdx.x;
    if (idx >= BQ * TFEAT * SEQ) return;
    int s = idx & (SEQ - 1);
    int r = idx >> 9;
    int f = r % TFEAT;
    int b = r / TFEAT;
    tok[((size_t)(b * LTOK + NVAR + f)) * SEQ + s] = x_mark[((size_t)(b * SEQ + s)) * TFEAT + f];
}

// ---------------- combined x_proj/dt_proj weight prep ----------------
__global__ void prep_wd(const float* __restrict__ xpw, const float* __restrict__ dpw,
                        float* __restrict__ out)
{
    int ld = blockIdx.y;                       // 0..3 = l*2+dir
    int idx = blockIdx.x * 256 + threadIdx.x;  // 160*128
    if (idx >= 160 * DMOD) return;
    int i = idx / DMOD, j = idx - i * DMOD;
    const float* xp = xpw + ld * 40 * DMOD;
    float v;
    if (i < DMOD) {
        const float* dp = dpw + (ld * DMOD + i) * 8;
        v = 0.f;
        #pragma unroll
        for (int r = 0; r < 8; r++) v += dp[r] * xp[r * DMOD + j];
    } else {
        v = xp[(8 + (i - DMOD)) * DMOD + j];
    }
    out[ld * 160 * DMOD + idx] = v;
}

// ---------------- out_proj weight concat: W'[l][n][k] ----------------
__global__ void prep_wop(const float* __restrict__ opw, float* __restrict__ out)
{
    int idx = blockIdx.x * 256 + threadIdx.x;  // 2*128*256
    if (idx >= 2 * DMOD * 256) return;
    int l = idx / (DMOD * 256);
    int r = idx - l * DMOD * 256;
    int n = r >> 8;
    int k = r & 255;
    int dir = k >> 7;
    int kk = k & 127;
    out[idx] = opw[(((size_t)(l * 2 + dir) * DMOD) + n) * DMOD + kk];
}

// ---------------- fp32 GEMM: C[M,N] = A[M,K] @ W[N,K]^T (+epilogue) --------------
// BM=64, BN=128, BK=8, 256 threads, thread tile 4x8, double-buffered smem.
// EPI: 0 = (+bias if given)   1 = relu(v+bias)   2 = v + (bias?) + resid
//      3 = xproj: n<128 -> softplus(v + bias[n]); else raw
template<int EPI>
__global__ __launch_bounds__(256) void gemm_k(
    const float* __restrict__ A, const float* __restrict__ W,
    const float* __restrict__ bias, const float* __restrict__ resid,
    float* __restrict__ C, int M, int N, int K,
    size_t sA, size_t sW, size_t sB, size_t sC)
{
    if (gridDim.z > 1) {
        A += (size_t)blockIdx.z * sA;
        W += (size_t)blockIdx.z * sW;
        C += (size_t)blockIdx.z * sC;
        if (bias)  bias  += (size_t)blockIdx.z * sB;
        if (resid) resid += (size_t)blockIdx.z * sC;
    }
    __shared__ float As[2][8][64];
    __shared__ float Ws[2][8][128];
    int bm = blockIdx.y * 64;
    int bn = blockIdx.x * 128;
    int tid = threadIdx.x;
    int tx = tid & 15, ty = tid >> 4;

    int ar = tid >> 1, ac = (tid & 1) * 4;   // A loader (tid<128): rows 0..63
    bool aact = (tid < 128) && (bm + ar < M);
    int wr = tid >> 1, wc = (tid & 1) * 4;   // W loader (all): rows 0..127
    bool wact = (bn + wr < N);

    const float* Ap = A + (size_t)(bm + ar) * K + ac;
    const float* Wp = W + (size_t)(bn + wr) * K + wc;

    float acc[4][8] = {};
    float4 ra = make_float4(0.f,0.f,0.f,0.f), rw = make_float4(0.f,0.f,0.f,0.f);

    if (aact) ra = *(const float4*)(Ap);
    if (wact) rw = *(const float4*)(Wp);
    if (tid < 128) {
        As[0][ac+0][ar] = ra.x; As[0][ac+1][ar] = ra.y;
        As[0][ac+2][ar] = ra.z; As[0][ac+3][ar] = ra.w;
    }
    Ws[0][wc+0][wr] = rw.x; Ws[0][wc+1][wr] = rw.y;
    Ws[0][wc+2][wr] = rw.z; Ws[0][wc+3][wr] = rw.w;
    __syncthreads();

    int NT = K >> 3;
    for (int t = 0; t < NT; t++) {
        int buf = t & 1;
        if (t + 1 < NT) {
            int k0 = (t + 1) << 3;
            if (aact) ra = *(const float4*)(Ap + k0);
            if (wact) rw = *(const float4*)(Wp + k0);
        }
        #pragma unroll
        for (int kk = 0; kk < 8; kk++) {
            float4 a0 = *(const float4*)&As[buf][kk][ty * 4];
            float4 w0 = *(const float4*)&Ws[buf][kk][tx * 8];
            float4 w1 = *(const float4*)&Ws[buf][kk][tx * 8 + 4];
            float av[4] = {a0.x, a0.y, a0.z, a0.w};
            float wv[8] = {w0.x, w0.y, w0.z, w0.w, w1.x, w1.y, w1.z, w1.w};
            #pragma unroll
            for (int i = 0; i < 4; i++)
                #pragma unroll
                for (int j = 0; j < 8; j++)
                    acc[i][j] = fmaf(av[i], wv[j], acc[i][j]);
        }
        if (t + 1 < NT) {
            int nb = buf ^ 1;
            if (tid < 128) {
                As[nb][ac+0][ar] = ra.x; As[nb][ac+1][ar] = ra.y;
                As[nb][ac+2][ar] = ra.z; As[nb][ac+3][ar] = ra.w;
            }
            Ws[nb][wc+0][wr] = rw.x; Ws[nb][wc+1][wr] = rw.y;
            Ws[nb][wc+2][wr] = rw.z; Ws[nb][wc+3][wr] = rw.w;
            __syncthreads();
        }
    }

    #pragma unroll
    for (int i = 0; i < 4; i++) {
        int m = bm + ty * 4 + i;
        if (m >= M) continue;
        #pragma unroll
        for (int j = 0; j < 8; j++) {
            int n = bn + tx * 8 + j;
            if (n >= N) continue;
            float v = acc[i][j];
            if (EPI == 0) {
                if (bias) v += bias[n];
            } else if (EPI == 1) {
                v = fmaxf(v + bias[n], 0.f);
            } else if (EPI == 2) {
                if (bias) v += bias[n];
                v += resid[(size_t)m * N + n];
            } else if (EPI == 3) {
                if (n < DMOD) {
                    v += bias[n];
                    v = (v > 20.f) ? v : log1pf(__expf(v));
                }
            }
            C[(size_t)m * N + n] = v;
        }
    }
}

// ---------------- depthwise causal conv (DCONV=2) + silu, scan-time order --------
__global__ void conv_silu(const float* __restrict__ xz, const float* __restrict__ cw,
                          const float* __restrict__ cb, float* __restrict__ xc, int l)
{
    int idx = blockIdx.x * 256 + threadIdx.x;
    if (idx >= 2 * MTOT * DMOD) return;
    int dir = idx / (MTOT * DMOD);
    int rem = idx - dir * (MTOT * DMOD);
    int row = rem >> 7;              // b*LTOK + tau
    int d = rem & (DMOD - 1);
    int b = row / LTOK;
    int tau = row - b * LTOK;
    int t = dir ? (LTOK - 1 - tau) : tau;
    int ld = l * 2 + dir;
    float c0 = cw[(ld * DMOD + d) * 2 + 0];
    float c1 = cw[(ld * DMOD + d) * 2 + 1];
    float x1 = xz[((size_t)(b * LTOK + t)) * 512 + dir * 256 + d];
    float acc = x1 * c1 + cb[ld * DMOD + d];
    if (tau > 0) {
        int tp = dir ? (t + 1) : (t - 1);
        acc += xz[((size_t)(b * LTOK + tp)) * 512 + dir * 256 + d] * c0;
    }
    acc = acc / (1.f + __expf(-acc));     // silu
    xc[(size_t)dir * MTOT * DMOD + rem] = acc;
}

// ---------------- selective scan ----------------
__global__ __launch_bounds__(256) void scan_k(
    const float* __restrict__ dbc, const float* __restrict__ xc,
    const float* __restrict__ xz, const float* __restrict__ A_log,
    const float* __restrict__ Dpar, float* __restrict__ y, int l)
{
    int n  = threadIdx.x & 15;
    int dl = threadIdx.x >> 4;
    int d  = blockIdx.x * 16 + dl;
    int b  = blockIdx.y;
    int dir = blockIdx.z;
    int ld = l * 2 + dir;

    float a  = -__expf(A_log[(ld * DMOD + d) * DST + n]);
    float Dp = Dpar[ld * DMOD + d];

    const float* dbcp = dbc + (size_t)dir * MTOT * 160 + (size_t)b * LTOK * 160;
    const float* xcp  = xc  + (size_t)dir * MTOT * DMOD + (size_t)b * LTOK * DMOD;
    const float* zp   = xz  + (size_t)b * LTOK * 512 + 128 + dir * 256;
    float*       yp   = y   + (size_t)b * LTOK * 256 + dir * 128;

    float hst = 0.f;
    #pragma unroll 2
    for (int tau = 0; tau < LTOK; tau++) {
        const float* row = dbcp + (size_t)tau * 160;
        float delta = row[d];
        float Bv    = row[128 + n];
        float Cv    = row[144 + n];
        float xcv   = xcp[(size_t)tau * DMOD + d];
        float dA = __expf(delta * a);
        hst = fmaf(dA, hst, delta * Bv * xcv);
        float p = hst * Cv;
        p += __shfl_xor_sync(0xffffffffu, p, 8);
        p += __shfl_xor_sync(0xffffffffu, p, 4);
        p += __shfl_xor_sync(0xffffffffu, p, 2);
        p += __shfl_xor_sync(0xffffffffu, p, 1);
        if (n == 0) {
            int t = dir ? (LTOK - 1 - tau) : tau;
            float z = zp[(size_t)t * 512 + d];
            float sz = z / (1.f + __expf(-z));
            yp[(size_t)t * 256 + d] = (p + Dp * xcv) * sz;
        }
    }
}

// ---------------- layernorm over last dim (128) ----------------
__global__ void ln_k(const float* __restrict__ in, float* __restrict__ out,
                     const float* __restrict__ w, const float* __restrict__ b)
{
    int row = blockIdx.x;
    int t = threadIdx.x;
    float v = in[(size_t)row * DMOD + t];
    __shared__ float sm[4], sm2[4];
    float s = v;
    #pragma unroll
    for (int o = 16; o; o >>= 1) s += __shfl_xor_sync(0xffffffffu, s, o);
    if ((t & 31) == 0) sm[t >> 5] = s;
    __syncthreads();
    float mu = (sm[0] + sm[1] + sm[2] + sm[3]) * (1.f / 128.f);
    float dv = v - mu;
    float q = dv * dv;
    #pragma unroll
    for (int o = 16; o; o >>= 1) q += __shfl_xor_sync(0xffffffffu, q, o);
    if ((t & 31) == 0) sm2[t >> 5] = q;
    __syncthreads();
    float var = (sm2[0] + sm2[1] + sm2[2] + sm2[3]) * (1.f / 128.f);
    out[(size_t)row * DMOD + t] = dv * rsqrtf(var + 1e-5f) * w[t] + b[t];
}

// ---------------- final transposed write ----------------
__global__ void write_out(const float* __restrict__ P, float* __restrict__ out)
{
    int idx = blockIdx.x * 256 + threadIdx.x;
    if (idx >= BQ * PREDN * NVAR) return;
    int v = idx & (NVAR - 1);
    int p = (idx >> 10) % PREDN;
    int b = idx / (PREDN * NVAR);
    out[idx] = P[((size_t)(b * LTOK + v)) * PREDN + p];
}

// ---------------- launcher ----------------
extern "C" void kernel_launch(void* const* d_in, const int* in_sizes, int n_in,
                              void* d_out, int out_size)
{
    const float* x_enc     = (const float*)d_in[0];
    const float* x_mark    = (const float*)d_in[1];
    const float* emb_w     = (const float*)d_in[4];
    const float* emb_b     = (const float*)d_in[5];
    const float* in_proj_w = (const float*)d_in[6];
    const float* conv_w    = (const float*)d_in[7];
    const float* conv_b    = (const float*)d_in[8];
    const float* x_proj_w  = (const float*)d_in[9];
    const float* dt_proj_w = (const float*)d_in[10];
    const float* dt_proj_b = (const float*)d_in[11];
    const float* A_log     = (const float*)d_in[12];
    const float* D_param   = (const float*)d_in[13];
    const float* out_projw = (const float*)d_in[14];
    const float* norm1_w   = (const float*)d_in[15];
    const float* norm1_b   = (const float*)d_in[16];
    const float* norm2_w   = (const float*)d_in[17];
    const float* norm2_b   = (const float*)d_in[18];
    const float* ffn_w1    = (const float*)d_in[19];
    const float* ffn_b1    = (const float*)d_in[20];
    const float* ffn_w2    = (const float*)d_in[21];
    const float* ffn_b2    = (const float*)d_in[22];
    const float* fnorm_w   = (const float*)d_in[23];
    const float* fnorm_b   = (const float*)d_in[24];
    const float* proj_w    = (const float*)d_in[25];
    const float* proj_b    = (const float*)d_in[26];

    float *ptok, *ph, *pln1, *pffn, *pxz, *pxc, *pdbc, *py, *ppo, *pwxp, *pwop;
    cudaGetSymbolAddress((void**)&ptok, g_tok);
    cudaGetSymbolAddress((void**)&ph,   g_h);
    cudaGetSymbolAddress((void**)&pln1, g_ln1);
    cudaGetSymbolAddress((void**)&pffn, g_ffn);
    cudaGetSymbolAddress((void**)&pxz,  g_xz);
    cudaGetSymbolAddress((void**)&pxc,  g_xc);
    cudaGetSymbolAddress((void**)&pdbc, g_dbc);
    cudaGetSymbolAddress((void**)&py,   g_y);
    cudaGetSymbolAddress((void**)&ppo,  g_po);
    cudaGetSymbolAddress((void**)&pwxp, g_wxp);
    cudaGetSymbolAddress((void**)&pwop, g_wop);

    const int MT = (MTOT + 63) / 64;   // 129

    prep_wd<<<dim3(80, 4), 256>>>(x_proj_w, dt_proj_w, pwxp);
    prep_wop<<<(2 * DMOD * 256 + 255) / 256, 256>>>(out_projw, pwop);
    tok_prep<<<dim3(SEQ / 32, NVAR / 32, BQ), dim3(32, 8)>>>(x_enc, ptok);
    mark_prep<<<(BQ * TFEAT * SEQ + 255) / 256, 256>>>(x_mark, ptok);

    // embedding: h = tok @ emb_w^T + b     (M=MTOT, N=128, K=512)
    gemm_k<0><<<dim3(1, MT), 256>>>(ptok, emb_w, emb_b, nullptr, ph,
                                    MTOT, DMOD, SEQ, 0, 0, 0, 0);

    for (int l = 0; l < 2; l++) {
        // in_proj both directions: h(M,128) @ W(512,128)^T
        gemm_k<0><<<dim3(4, MT), 256>>>(ph, in_proj_w + (size_t)l * 2 * 256 * DMOD,
                                        nullptr, nullptr, pxz, MTOT, 512, DMOD, 0, 0, 0, 0);
        conv_silu<<<(2 * MTOT * DMOD + 255) / 256, 256>>>(pxz, conv_w, conv_b, pxc, l);
        // xproj fused (softplus epilogue), batched over dirs via grid.z
        gemm_k<3><<<dim3(2, MT, 2), 256>>>(pxc, pwxp + (size_t)l * 2 * 160 * DMOD,
                                           dt_proj_b + (size_t)l * 2 * DMOD, nullptr, pdbc,
                                           MTOT, 160, DMOD,
                                           (size_t)MTOT * DMOD, (size_t)160 * DMOD,
                                           (size_t)DMOD, (size_t)MTOT * 160);
        scan_k<<<dim3(8, 8, 2), 256>>>(pdbc, pxc, pxz, A_log, D_param, py, l);
        // fused out_proj (both dirs, K=256) + residual into h
        gemm_k<2><<<dim3(1, MT), 256>>>(py, pwop + (size_t)l * DMOD * 256,
                                        nullptr, ph, ph, MTOT, DMOD, 256, 0, 0, 0, 0);
        ln_k<<<MTOT, 128>>>(ph, pln1, norm1_w + l * DMOD, norm1_b + l * DMOD);
        gemm_k<1><<<dim3(1, MT), 256>>>(pln1, ffn_w1 + (size_t)l * DMOD * DMOD,
                                        ffn_b1 + l * DMOD, nullptr, pffn,
                                        MTOT, DMOD, DMOD, 0, 0, 0, 0);
        gemm_k<2><<<dim3(1, MT), 256>>>(pffn, ffn_w2 + (size_t)l * DMOD * DMOD,
                                        ffn_b2 + l * DMOD, pln1, ph, MTOT, DMOD, DMOD, 0, 0, 0, 0);
        ln_k<<<MTOT, 128>>>(ph, ph, norm2_w + l * DMOD, norm2_b + l * DMOD);
    }

    ln_k<<<MTOT, 128>>>(ph, pln1, fnorm_w, fnorm_b);
    gemm_k<0><<<dim3(1, MT), 256>>>(pln1, proj_w, proj_b, nullptr, ppo,
                                    MTOT, PREDN, DMOD, 0, 0, 0, 0);
    write_out<<<(BQ * PREDN * NVAR + 255) / 256, 256>>>(ppo, (float*)d_out);
}

// round 4
// speedup vs baseline: 2.4435x; 2.4435x over previous
#include <cuda_runtime.h>
#include <math.h>

#define BQ    8
#define SEQ   512
#define NVAR  1024
#define TFEAT 7
#define LTOK  1031           // NVAR + TFEAT
#define MTOT  8248           // BQ * LTOK
#define DMOD  128
#define DST   16
#define PREDN 96
#define NCH   16
#define CLEN  65             // ceil(LTOK/NCH)

// ---------------- scratch (device globals; no allocation allowed) ----------------
__device__ float g_tok[MTOT * SEQ];          // masked, transposed tokens [m][s]
__device__ float g_h  [MTOT * DMOD];
__device__ float g_ln1[MTOT * DMOD];
__device__ float g_ffn[MTOT * DMOD];
__device__ float g_xz [MTOT * 512];          // [m][0:128 xr_f |128:256 z_f |256:384 xr_r |384:512 z_r]
__device__ float g_xc [2 * MTOT * DMOD];     // per dir, scan-time order
__device__ float g_dbc[2 * MTOT * 160];      // per dir: delta(128) B(16) C(16), scan-time order
__device__ float g_y  [MTOT * 256];          // scan output, ORIGINAL order, [m][dir*128+d]
__device__ float g_po [MTOT * PREDN];
__device__ float g_wxp[4 * 160 * DMOD];      // per (l,dir): rows0-127 = dpw@xpw[:8]; 128-159 = xpw[8:40]
__device__ float g_wop[2 * DMOD * 256];      // per l: out_proj concat over dirs along K
__device__ float g_sA [BQ * 2 * NCH * DMOD * DST];   // per-chunk prod(dA)
__device__ float g_sH [BQ * 2 * NCH * DMOD * DST];   // per-chunk local end state
__device__ float g_sS [BQ * 2 * NCH * DMOD * DST];   // per-chunk true start state

// ---------------- token transpose + mask: x_enc[b][s][v] -> tok[b*LTOK+v][s] -----
__global__ void tok_prep(const float* __restrict__ x_enc, float* __restrict__ tok)
{
    __shared__ float tile[32][33];
    int b = blockIdx.z;
    int s0 = blockIdx.x * 32, v0 = blockIdx.y * 32;
    #pragma unroll
    for (int i = 0; i < 4; i++) {
        int s = s0 + threadIdx.y + i * 8;
        float x = x_enc[((size_t)(b * SEQ + s)) * NVAR + v0 + threadIdx.x];
        tile[threadIdx.y + i * 8][threadIdx.x] = (x == -9999.0f) ? -1.0f : x;
    }
    __syncthreads();
    #pragma unroll
    for (int i = 0; i < 4; i++) {
        int v = v0 + threadIdx.y + i * 8;
        tok[((size_t)(b * LTOK + v)) * SEQ + s0 + threadIdx.x] = tile[threadIdx.x][threadIdx.y + i * 8];
    }
}

__global__ void mark_prep(const float* __restrict__ x_mark, float* __restrict__ tok)
{
    int idx = blockIdx.x * 256 + threadIdx.x;
    if (idx >= BQ * TFEAT * SEQ) return;
    int s = idx & (SEQ - 1);
    int r = idx >> 9;
    int f = r % TFEAT;
    int b = r / TFEAT;
    tok[((size_t)(b * LTOK + NVAR + f)) * SEQ + s] = x_mark[((size_t)(b * SEQ + s)) * TFEAT + f];
}

// ---------------- combined x_proj/dt_proj weight prep ----------------
__global__ void prep_wd(const float* __restrict__ xpw, const float* __restrict__ dpw,
                        float* __restrict__ out)
{
    int ld = blockIdx.y;                       // 0..3 = l*2+dir
    int idx = blockIdx.x * 256 + threadIdx.x;  // 160*128
    if (idx >= 160 * DMOD) return;
    int i = idx / DMOD, j = idx - i * DMOD;
    const float* xp = xpw + ld * 40 * DMOD;
    float v;
    if (i < DMOD) {
        const float* dp = dpw + (ld * DMOD + i) * 8;
        v = 0.f;
        #pragma unroll
        for (int r = 0; r < 8; r++) v += dp[r] * xp[r * DMOD + j];
    } else {
        v = xp[(8 + (i - DMOD)) * DMOD + j];
    }
    out[ld * 160 * DMOD + idx] = v;
}

// ---------------- out_proj weight concat: W'[l][n][k] ----------------
__global__ void prep_wop(const float* __restrict__ opw, float* __restrict__ out)
{
    int idx = blockIdx.x * 256 + threadIdx.x;  // 2*128*256
    if (idx >= 2 * DMOD * 256) return;
    int l = idx / (DMOD * 256);
    int r = idx - l * DMOD * 256;
    int n = r >> 8;
    int k = r & 255;
    int dir = k >> 7;
    int kk = k & 127;
    out[idx] = opw[(((size_t)(l * 2 + dir) * DMOD) + n) * DMOD + kk];
}

// ---------------- fp32 GEMM: C[M,N] = A[M,K] @ W[N,K]^T (+epilogue) --------------
// BM=64, BN=128, BK=8, 256 threads, thread tile 4x8, double-buffered smem.
template<int EPI>
__global__ __launch_bounds__(256) void gemm_k(
    const float* __restrict__ A, const float* __restrict__ W,
    const float* __restrict__ bias, const float* __restrict__ resid,
    float* __restrict__ C, int M, int N, int K,
    size_t sA, size_t sW, size_t sB, size_t sC)
{
    if (gridDim.z > 1) {
        A += (size_t)blockIdx.z * sA;
        W += (size_t)blockIdx.z * sW;
        C += (size_t)blockIdx.z * sC;
        if (bias)  bias  += (size_t)blockIdx.z * sB;
        if (resid) resid += (size_t)blockIdx.z * sC;
    }
    __shared__ float As[2][8][64];
    __shared__ float Ws[2][8][128];
    int bm = blockIdx.y * 64;
    int bn = blockIdx.x * 128;
    int tid = threadIdx.x;
    int tx = tid & 15, ty = tid >> 4;

    int ar = tid >> 1, ac = (tid & 1) * 4;
    bool aact = (tid < 128) && (bm + ar < M);
    int wr = tid >> 1, wc = (tid & 1) * 4;
    bool wact = (bn + wr < N);

    const float* Ap = A + (size_t)(bm + ar) * K + ac;
    const float* Wp = W + (size_t)(bn + wr) * K + wc;

    float acc[4][8] = {};
    float4 ra = make_float4(0.f,0.f,0.f,0.f), rw = make_float4(0.f,0.f,0.f,0.f);

    if (aact) ra = *(const float4*)(Ap);
    if (wact) rw = *(const float4*)(Wp);
    if (tid < 128) {
        As[0][ac+0][ar] = ra.x; As[0][ac+1][ar] = ra.y;
        As[0][ac+2][ar] = ra.z; As[0][ac+3][ar] = ra.w;
    }
    Ws[0][wc+0][wr] = rw.x; Ws[0][wc+1][wr] = rw.y;
    Ws[0][wc+2][wr] = rw.z; Ws[0][wc+3][wr] = rw.w;
    __syncthreads();

    int NT = K >> 3;
    for (int t = 0; t < NT; t++) {
        int buf = t & 1;
        if (t + 1 < NT) {
            int k0 = (t + 1) << 3;
            if (aact) ra = *(const float4*)(Ap + k0);
            if (wact) rw = *(const float4*)(Wp + k0);
        }
        #pragma unroll
        for (int kk = 0; kk < 8; kk++) {
            float4 a0 = *(const float4*)&As[buf][kk][ty * 4];
            float4 w0 = *(const float4*)&Ws[buf][kk][tx * 8];
            float4 w1 = *(const float4*)&Ws[buf][kk][tx * 8 + 4];
            float av[4] = {a0.x, a0.y, a0.z, a0.w};
            float wv[8] = {w0.x, w0.y, w0.z, w0.w, w1.x, w1.y, w1.z, w1.w};
            #pragma unroll
            for (int i = 0; i < 4; i++)
                #pragma unroll
                for (int j = 0; j < 8; j++)
                    acc[i][j] = fmaf(av[i], wv[j], acc[i][j]);
        }
        if (t + 1 < NT) {
            int nb = buf ^ 1;
            if (tid < 128) {
                As[nb][ac+0][ar] = ra.x; As[nb][ac+1][ar] = ra.y;
                As[nb][ac+2][ar] = ra.z; As[nb][ac+3][ar] = ra.w;
            }
            Ws[nb][wc+0][wr] = rw.x; Ws[nb][wc+1][wr] = rw.y;
            Ws[nb][wc+2][wr] = rw.z; Ws[nb][wc+3][wr] = rw.w;
            __syncthreads();
        }
    }

    #pragma unroll
    for (int i = 0; i < 4; i++) {
        int m = bm + ty * 4 + i;
        if (m >= M) continue;
        #pragma unroll
        for (int j = 0; j < 8; j++) {
            int n = bn + tx * 8 + j;
            if (n >= N) continue;
            float v = acc[i][j];
            if (EPI == 0) {
                if (bias) v += bias[n];
            } else if (EPI == 1) {
                v = fmaxf(v + bias[n], 0.f);
            } else if (EPI == 2) {
                if (bias) v += bias[n];
                v += resid[(size_t)m * N + n];
            } else if (EPI == 3) {
                if (n < DMOD) {
                    v += bias[n];
                    v = (v > 20.f) ? v : log1pf(__expf(v));
                }
            }
            C[(size_t)m * N + n] = v;
        }
    }
}

// ---------------- depthwise causal conv (DCONV=2) + silu, scan-time order --------
__global__ void conv_silu(const float* __restrict__ xz, const float* __restrict__ cw,
                          const float* __restrict__ cb, float* __restrict__ xc, int l)
{
    int idx = blockIdx.x * 256 + threadIdx.x;
    if (idx >= 2 * MTOT * DMOD) return;
    int dir = idx / (MTOT * DMOD);
    int rem = idx - dir * (MTOT * DMOD);
    int row = rem >> 7;              // b*LTOK + tau
    int d = rem & (DMOD - 1);
    int b = row / LTOK;
    int tau = row - b * LTOK;
    int t = dir ? (LTOK - 1 - tau) : tau;
    int ld = l * 2 + dir;
    float c0 = cw[(ld * DMOD + d) * 2 + 0];
    float c1 = cw[(ld * DMOD + d) * 2 + 1];
    float x1 = xz[((size_t)(b * LTOK + t)) * 512 + dir * 256 + d];
    float acc = x1 * c1 + cb[ld * DMOD + d];
    if (tau > 0) {
        int tp = dir ? (t + 1) : (t - 1);
        acc += xz[((size_t)(b * LTOK + tp)) * 512 + dir * 256 + d] * c0;
    }
    acc = acc / (1.f + __expf(-acc));     // silu
    xc[(size_t)dir * MTOT * DMOD + rem] = acc;
}

// ---------------- chunked selective scan ----------------
// state layout: idx = (((b*2+dir)*NCH + c)*DMOD + d)*DST + n

// pass1: per-chunk local scan; store prod(dA) and local end h
__global__ __launch_bounds__(256) void scan_p1(
    const float* __restrict__ dbc, const float* __restrict__ xc,
    const float* __restrict__ A_log, float* __restrict__ sA, float* __restrict__ sH, int l)
{
    int n  = threadIdx.x & 15;
    int dl = threadIdx.x >> 4;
    int d  = blockIdx.x * 16 + dl;
    int b  = blockIdx.y;
    int z  = blockIdx.z;
    int dir = z >> 4;
    int c   = z & 15;
    int ld = l * 2 + dir;

    float a = -__expf(A_log[(ld * DMOD + d) * DST + n]);
    const float* dbcp = dbc + (size_t)dir * MTOT * 160 + (size_t)b * LTOK * 160;
    const float* xcp  = xc  + (size_t)dir * MTOT * DMOD + (size_t)b * LTOK * DMOD;

    int t0 = c * CLEN;
    int t1 = t0 + CLEN; if (t1 > LTOK) t1 = LTOK;

    float Aacc = 1.f, h = 0.f;
    for (int t = t0; t < t1; t++) {
        const float* row = dbcp + (size_t)t * 160;
        float delta = row[d];
        float Bv    = row[128 + n];
        float xcv   = xcp[(size_t)t * DMOD + d];
        float dA = __expf(delta * a);
        Aacc *= dA;
        h = fmaf(dA, h, delta * Bv * xcv);
    }
    size_t idx = (((size_t)(b * 2 + dir) * NCH + c) * DMOD + d) * DST + n;
    sA[idx] = Aacc;
    sH[idx] = h;
}

// combine: sequential over the 16 chunks, store true start state per chunk
__global__ void scan_comb(const float* __restrict__ sA, const float* __restrict__ sH,
                          float* __restrict__ sS)
{
    int idx = blockIdx.x * 256 + threadIdx.x;        // over BQ*2*DMOD*DST = 32768
    if (idx >= BQ * 2 * DMOD * DST) return;
    int dn = idx & (DMOD * DST - 1);                 // d*16+n
    int bd = idx >> 11;                              // b*2+dir
    size_t base = (size_t)bd * NCH * DMOD * DST + dn;
    float h = 0.f;
    #pragma unroll
    for (int c = 0; c < NCH; c++) {
        size_t p = base + (size_t)c * DMOD * DST;
        sS[p] = h;
        h = fmaf(sA[p], h, sH[p]);
    }
}

// pass2: re-scan chunk from true start state, compute y with silu(z) gate
__global__ __launch_bounds__(256) void scan_p2(
    const float* __restrict__ dbc, const float* __restrict__ xc,
    const float* __restrict__ xz, const float* __restrict__ A_log,
    const float* __restrict__ Dpar, const float* __restrict__ sS,
    float* __restrict__ y, int l)
{
    int n  = threadIdx.x & 15;
    int dl = threadIdx.x >> 4;
    int d  = blockIdx.x * 16 + dl;
    int b  = blockIdx.y;
    int z  = blockIdx.z;
    int dir = z >> 4;
    int c   = z & 15;
    int ld = l * 2 + dir;

    float a  = -__expf(A_log[(ld * DMOD + d) * DST + n]);
    float Dp = Dpar[ld * DMOD + d];
    const float* dbcp = dbc + (size_t)dir * MTOT * 160 + (size_t)b * LTOK * 160;
    const float* xcp  = xc  + (size_t)dir * MTOT * DMOD + (size_t)b * LTOK * DMOD;
    const float* zp   = xz  + (size_t)b * LTOK * 512 + 128 + dir * 256;
    float*       yp   = y   + (size_t)b * LTOK * 256 + dir * 128;

    int t0 = c * CLEN;
    int t1 = t0 + CLEN; if (t1 > LTOK) t1 = LTOK;

    float h = sS[(((size_t)(b * 2 + dir) * NCH + c) * DMOD + d) * DST + n];
    for (int tau = t0; tau < t1; tau++) {
        const float* row = dbcp + (size_t)tau * 160;
        float delta = row[d];
        float Bv    = row[128 + n];
        float Cv    = row[144 + n];
        float xcv   = xcp[(size_t)tau * DMOD + d];
        float dA = __expf(delta * a);
        h = fmaf(dA, h, delta * Bv * xcv);
        float p = h * Cv;
        p += __shfl_xor_sync(0xffffffffu, p, 8);
        p += __shfl_xor_sync(0xffffffffu, p, 4);
        p += __shfl_xor_sync(0xffffffffu, p, 2);
        p += __shfl_xor_sync(0xffffffffu, p, 1);
        if (n == 0) {
            int t = dir ? (LTOK - 1 - tau) : tau;
            float zv = zp[(size_t)t * 512 + d];
            float sz = zv / (1.f + __expf(-zv));
            yp[(size_t)t * 256 + d] = (p + Dp * xcv) * sz;
        }
    }
}

// ---------------- layernorm over last dim (128) ----------------
__global__ void ln_k(const float* __restrict__ in, float* __restrict__ out,
                     const float* __restrict__ w, const float* __restrict__ b)
{
    int row = blockIdx.x;
    int t = threadIdx.x;
    float v = in[(size_t)row * DMOD + t];
    __shared__ float sm[4], sm2[4];
    float s = v;
    #pragma unroll
    for (int o = 16; o; o >>= 1) s += __shfl_xor_sync(0xffffffffu, s, o);
    if ((t & 31) == 0) sm[t >> 5] = s;
    __syncthreads();
    float mu = (sm[0] + sm[1] + sm[2] + sm[3]) * (1.f / 128.f);
    float dv = v - mu;
    float q = dv * dv;
    #pragma unroll
    for (int o = 16; o; o >>= 1) q += __shfl_xor_sync(0xffffffffu, q, o);
    if ((t & 31) == 0) sm2[t >> 5] = q;
    __syncthreads();
    float var = (sm2[0] + sm2[1] + sm2[2] + sm2[3]) * (1.f / 128.f);
    out[(size_t)row * DMOD + t] = dv * rsqrtf(var + 1e-5f) * w[t] + b[t];
}

// ---------------- final transposed write ----------------
__global__ void write_out(const float* __restrict__ P, float* __restrict__ out)
{
    int idx = blockIdx.x * 256 + threadIdx.x;
    if (idx >= BQ * PREDN * NVAR) return;
    int v = idx & (NVAR - 1);
    int p = (idx >> 10) % PREDN;
    int b = idx / (PREDN * NVAR);
    out[idx] = P[((size_t)(b * LTOK + v)) * PREDN + p];
}

// ---------------- launcher ----------------
extern "C" void kernel_launch(void* const* d_in, const int* in_sizes, int n_in,
                              void* d_out, int out_size)
{
    const float* x_enc     = (const float*)d_in[0];
    const float* x_mark    = (const float*)d_in[1];
    const float* emb_w     = (const float*)d_in[4];
    const float* emb_b     = (const float*)d_in[5];
    const float* in_proj_w = (const float*)d_in[6];
    const float* conv_w    = (const float*)d_in[7];
    const float* conv_b    = (const float*)d_in[8];
    const float* x_proj_w  = (const float*)d_in[9];
    const float* dt_proj_w = (const float*)d_in[10];
    const float* dt_proj_b = (const float*)d_in[11];
    const float* A_log     = (const float*)d_in[12];
    const float* D_param   = (const float*)d_in[13];
    const float* out_projw = (const float*)d_in[14];
    const float* norm1_w   = (const float*)d_in[15];
    const float* norm1_b   = (const float*)d_in[16];
    const float* norm2_w   = (const float*)d_in[17];
    const float* norm2_b   = (const float*)d_in[18];
    const float* ffn_w1    = (const float*)d_in[19];
    const float* ffn_b1    = (const float*)d_in[20];
    const float* ffn_w2    = (const float*)d_in[21];
    const float* ffn_b2    = (const float*)d_in[22];
    const float* fnorm_w   = (const float*)d_in[23];
    const float* fnorm_b   = (const float*)d_in[24];
    const float* proj_w    = (const float*)d_in[25];
    const float* proj_b    = (const float*)d_in[26];

    float *ptok, *ph, *pln1, *pffn, *pxz, *pxc, *pdbc, *py, *ppo, *pwxp, *pwop;
    float *psA, *psH, *psS;
    cudaGetSymbolAddress((void**)&ptok, g_tok);
    cudaGetSymbolAddress((void**)&ph,   g_h);
    cudaGetSymbolAddress((void**)&pln1, g_ln1);
    cudaGetSymbolAddress((void**)&pffn, g_ffn);
    cudaGetSymbolAddress((void**)&pxz,  g_xz);
    cudaGetSymbolAddress((void**)&pxc,  g_xc);
    cudaGetSymbolAddress((void**)&pdbc, g_dbc);
    cudaGetSymbolAddress((void**)&py,   g_y);
    cudaGetSymbolAddress((void**)&ppo,  g_po);
    cudaGetSymbolAddress((void**)&pwxp, g_wxp);
    cudaGetSymbolAddress((void**)&pwop, g_wop);
    cudaGetSymbolAddress((void**)&psA,  g_sA);
    cudaGetSymbolAddress((void**)&psH,  g_sH);
    cudaGetSymbolAddress((void**)&psS,  g_sS);

    const int MT = (MTOT + 63) / 64;   // 129

    // launch order chosen so that launch index 3 (the one ncu captures)
    // is the big in_proj GEMM of layer 0.
    tok_prep<<<dim3(SEQ / 32, NVAR / 32, BQ), dim3(32, 8)>>>(x_enc, ptok);          // 0
    mark_prep<<<(BQ * TFEAT * SEQ + 255) / 256, 256>>>(x_mark, ptok);               // 1
    gemm_k<0><<<dim3(1, MT), 256>>>(ptok, emb_w, emb_b, nullptr, ph,                // 2
                                    MTOT, DMOD, SEQ, 0, 0, 0, 0);
    gemm_k<0><<<dim3(4, MT), 256>>>(ph, in_proj_w, nullptr, nullptr, pxz,           // 3 (profiled)
                                    MTOT, 512, DMOD, 0, 0, 0, 0);
    prep_wd<<<dim3(80, 4), 256>>>(x_proj_w, dt_proj_w, pwxp);
    prep_wop<<<(2 * DMOD * 256 + 255) / 256, 256>>>(out_projw, pwop);

    for (int l = 0; l < 2; l++) {
        if (l > 0)
            gemm_k<0><<<dim3(4, MT), 256>>>(ph, in_proj_w + (size_t)l * 2 * 256 * DMOD,
                                            nullptr, nullptr, pxz, MTOT, 512, DMOD, 0, 0, 0, 0);
        conv_silu<<<(2 * MTOT * DMOD + 255) / 256, 256>>>(pxz, conv_w, conv_b, pxc, l);
        gemm_k<3><<<dim3(2, MT, 2), 256>>>(pxc, pwxp + (size_t)l * 2 * 160 * DMOD,
                                           dt_proj_b + (size_t)l * 2 * DMOD, nullptr, pdbc,
                                           MTOT, 160, DMOD,
                                           (size_t)MTOT * DMOD, (size_t)160 * DMOD,
                                           (size_t)DMOD, (size_t)MTOT * 160);
        scan_p1<<<dim3(8, BQ, 32), 256>>>(pdbc, pxc, A_log, psA, psH, l);
        scan_comb<<<(BQ * 2 * DMOD * DST + 255) / 256, 256>>>(psA, psH, psS);
        scan_p2<<<dim3(8, BQ, 32), 256>>>(pdbc, pxc, pxz, A_log, D_param, psS, py, l);
        gemm_k<2><<<dim3(1, MT), 256>>>(py, pwop + (size_t)l * DMOD * 256,
                                        nullptr, ph, ph, MTOT, DMOD, 256, 0, 0, 0, 0);
        ln_k<<<MTOT, 128>>>(ph, pln1, norm1_w + l * DMOD, norm1_b + l * DMOD);
        gemm_k<1><<<dim3(1, MT), 256>>>(pln1, ffn_w1 + (size_t)l * DMOD * DMOD,
                                        ffn_b1 + l * DMOD, nullptr, pffn,
                                        MTOT, DMOD, DMOD, 0, 0, 0, 0);
        gemm_k<2><<<dim3(1, MT), 256>>>(pffn, ffn_w2 + (size_t)l * DMOD * DMOD,
                                        ffn_b2 + l * DMOD, pln1, ph, MTOT, DMOD, DMOD, 0, 0, 0, 0);
        ln_k<<<MTOT, 128>>>(ph, ph, norm2_w + l * DMOD, norm2_b + l * DMOD);
    }

    ln_k<<<MTOT, 128>>>(ph, pln1, fnorm_w, fnorm_b);
    gemm_k<0><<<dim3(1, MT), 256>>>(pln1, proj_w, proj_b, nullptr, ppo,
                                    MTOT, PREDN, DMOD, 0, 0, 0, 0);
    write_out<<<(BQ * PREDN * NVAR + 255) / 256, 256>>>(ppo, (float*)d_out);
}

// round 5
// speedup vs baseline: 3.0868x; 1.2633x over previous
#include <cuda_runtime.h>
#include <math.h>

#define BQ    8
#define SEQ   512
#define NVAR  1024
#define TFEAT 7
#define LTOK  1031           // NVAR + TFEAT
#define MTOT  8248           // BQ * LTOK
#define DMOD  128
#define DST   16
#define PREDN 96
#define NCH   16
#define CLEN  65             // ceil(LTOK/NCH)

// ---------------- scratch (device globals; no allocation allowed) ----------------
__device__ float g_tok[MTOT * SEQ];
__device__ float g_h  [MTOT * DMOD];
__device__ float g_ln1[MTOT * DMOD];
__device__ float g_ffn[MTOT * DMOD];
__device__ float g_xz [MTOT * 512];
__device__ float g_xc [2 * MTOT * DMOD];
__device__ float g_dbc[2 * MTOT * 160];
__device__ float g_y  [MTOT * 256];
__device__ float g_po [MTOT * PREDN];
__device__ float g_wxp[4 * 160 * DMOD];
__device__ float g_wop[2 * DMOD * 256];
__device__ float g_sA [BQ * 2 * NCH * DMOD * DST];
__device__ float g_sH [BQ * 2 * NCH * DMOD * DST];
__device__ float g_sS [BQ * 2 * NCH * DMOD * DST];

// ---------------- token transpose + mask ----------------
__global__ void tok_prep(const float* __restrict__ x_enc, float* __restrict__ tok)
{
    __shared__ float tile[32][33];
    int b = blockIdx.z;
    int s0 = blockIdx.x * 32, v0 = blockIdx.y * 32;
    #pragma unroll
    for (int i = 0; i < 4; i++) {
        int s = s0 + threadIdx.y + i * 8;
        float x = x_enc[((size_t)(b * SEQ + s)) * NVAR + v0 + threadIdx.x];
        tile[threadIdx.y + i * 8][threadIdx.x] = (x == -9999.0f) ? -1.0f : x;
    }
    __syncthreads();
    #pragma unroll
    for (int i = 0; i < 4; i++) {
        int v = v0 + threadIdx.y + i * 8;
        tok[((size_t)(b * LTOK + v)) * SEQ + s0 + threadIdx.x] = tile[threadIdx.x][threadIdx.y + i * 8];
    }
}

__global__ void mark_prep(const float* __restrict__ x_mark, float* __restrict__ tok)
{
    int idx = blockIdx.x * 256 + threadIdx.x;
    if (idx >= BQ * TFEAT * SEQ) return;
    int s = idx & (SEQ - 1);
    int r = idx >> 9;
    int f = r % TFEAT;
    int b = r / TFEAT;
    tok[((size_t)(b * LTOK + NVAR + f)) * SEQ + s] = x_mark[((size_t)(b * SEQ + s)) * TFEAT + f];
}

// ---------------- combined x_proj/dt_proj weight prep ----------------
__global__ void prep_wd(const float* __restrict__ xpw, const float* __restrict__ dpw,
                        float* __restrict__ out)
{
    int ld = blockIdx.y;
    int idx = blockIdx.x * 256 + threadIdx.x;
    if (idx >= 160 * DMOD) return;
    int i = idx / DMOD, j = idx - i * DMOD;
    const float* xp = xpw + ld * 40 * DMOD;
    float v;
    if (i < DMOD) {
        const float* dp = dpw + (ld * DMOD + i) * 8;
        v = 0.f;
        #pragma unroll
        for (int r = 0; r < 8; r++) v += dp[r] * xp[r * DMOD + j];
    } else {
        v = xp[(8 + (i - DMOD)) * DMOD + j];
    }
    out[ld * 160 * DMOD + idx] = v;
}

// ---------------- out_proj weight concat ----------------
__global__ void prep_wop(const float* __restrict__ opw, float* __restrict__ out)
{
    int idx = blockIdx.x * 256 + threadIdx.x;
    if (idx >= 2 * DMOD * 256) return;
    int l = idx / (DMOD * 256);
    int r = idx - l * DMOD * 256;
    int n = r >> 8;
    int k = r & 255;
    int dir = k >> 7;
    int kk = k & 127;
    out[idx] = opw[(((size_t)(l * 2 + dir) * DMOD) + n) * DMOD + kk];
}

// ---------------- fp32 GEMM: C[M,N] = A[M,K] @ W[N,K]^T (+epilogue) --------------
// BM=128, BN=64, BK=16, 256 threads, warp grid 4x2 (32x32 warp tile), 8x4/thread.
template<int EPI>
__global__ __launch_bounds__(256) void gemm_k(
    const float* __restrict__ A, const float* __restrict__ W,
    const float* __restrict__ bias, const float* __restrict__ resid,
    float* __restrict__ C, int M, int N, int K,
    size_t sA, size_t sW, size_t sB, size_t sC)
{
    if (gridDim.z > 1) {
        A += (size_t)blockIdx.z * sA;
        W += (size_t)blockIdx.z * sW;
        C += (size_t)blockIdx.z * sC;
        if (bias)  bias  += (size_t)blockIdx.z * sB;
        if (resid) resid += (size_t)blockIdx.z * sC;
    }
    __shared__ float As[2][16][128];
    __shared__ float Bs[2][16][64];
    int bm = blockIdx.y * 128;
    int bn = blockIdx.x * 64;
    int tid = threadIdx.x;

    // compute mapping
    int wid = tid >> 5, lane = tid & 31;
    int warp_m = wid >> 1, warp_n = wid & 1;
    int lm = lane >> 3, ln = lane & 7;
    int mb  = warp_m * 32 + lm * 8;     // 8 rows
    int nbs = warp_n * 32 + ln * 4;     // 4 cols

    // A loader: thread -> row tid>>1 (0..127), two quads (tid&1)*2 + {0,1}
    int ar = tid >> 1;
    int ac = (tid & 1) * 8;             // float offset of first quad pair
    bool aact = (bm + ar < M);
    const float* Ap = A + (size_t)(bm + ar) * K + ac;

    // B loader: thread -> row tid>>2 (0..63), quad tid&3
    int br = tid >> 2;
    int bc = (tid & 3) * 4;
    bool wact = (bn + br < N);
    const float* Wp = W + (size_t)(bn + br) * K + bc;

    float acc[8][4] = {};
    float4 ra0 = make_float4(0,0,0,0), ra1 = make_float4(0,0,0,0), rw = make_float4(0,0,0,0);

    if (aact) { ra0 = *(const float4*)(Ap); ra1 = *(const float4*)(Ap + 4); }
    if (wact) { rw = *(const float4*)(Wp); }
    {
        float* as = &As[0][ac][ar];
        as[0*128] = ra0.x; as[1*128] = ra0.y; as[2*128] = ra0.z; as[3*128] = ra0.w;
        as[4*128] = ra1.x; as[5*128] = ra1.y; as[6*128] = ra1.z; as[7*128] = ra1.w;
        float* bs = &Bs[0][bc][br];
        bs[0*64] = rw.x; bs[1*64] = rw.y; bs[2*64] = rw.z; bs[3*64] = rw.w;
    }
    __syncthreads();

    int NT = K >> 4;
    for (int t = 0; t < NT; t++) {
        int buf = t & 1;
        if (t + 1 < NT) {
            int k0 = (t + 1) << 4;
            if (aact) { ra0 = *(const float4*)(Ap + k0); ra1 = *(const float4*)(Ap + k0 + 4); }
            if (wact) { rw = *(const float4*)(Wp + k0); }
        }
        #pragma unroll
        for (int k = 0; k < 16; k++) {
            float4 a0 = *(const float4*)&As[buf][k][mb];
            float4 a1 = *(const float4*)&As[buf][k][mb + 4];
            float4 b0 = *(const float4*)&Bs[buf][k][nbs];
            float av[8] = {a0.x, a0.y, a0.z, a0.w, a1.x, a1.y, a1.z, a1.w};
            float bv[4] = {b0.x, b0.y, b0.z, b0.w};
            #pragma unroll
            for (int i = 0; i < 8; i++)
                #pragma unroll
                for (int j = 0; j < 4; j++)
                    acc[i][j] = fmaf(av[i], bv[j], acc[i][j]);
        }
        if (t + 1 < NT) {
            int nb = buf ^ 1;
            float* as = &As[nb][ac][ar];
            as[0*128] = ra0.x; as[1*128] = ra0.y; as[2*128] = ra0.z; as[3*128] = ra0.w;
            as[4*128] = ra1.x; as[5*128] = ra1.y; as[6*128] = ra1.z; as[7*128] = ra1.w;
            float* bs = &Bs[nb][bc][br];
            bs[0*64] = rw.x; bs[1*64] = rw.y; bs[2*64] = rw.z; bs[3*64] = rw.w;
            __syncthreads();
        }
    }

    #pragma unroll
    for (int i = 0; i < 8; i++) {
        int m = bm + mb + i;
        if (m >= M) continue;
        #pragma unroll
        for (int j = 0; j < 4; j++) {
            int n = bn + nbs + j;
            if (n >= N) continue;
            float v = acc[i][j];
            if (EPI == 0) {
                if (bias) v += bias[n];
            } else if (EPI == 1) {
                v = fmaxf(v + bias[n], 0.f);
            } else if (EPI == 2) {
                if (bias) v += bias[n];
                v += resid[(size_t)m * N + n];
            } else if (EPI == 3) {
                if (n < DMOD) {
                    v += bias[n];
                    v = (v > 20.f) ? v : log1pf(__expf(v));
                }
            }
            C[(size_t)m * N + n] = v;
        }
    }
}

// ---------------- depthwise causal conv (DCONV=2) + silu ----------------
__global__ void conv_silu(const float* __restrict__ xz, const float* __restrict__ cw,
                          const float* __restrict__ cb, float* __restrict__ xc, int l)
{
    int idx = blockIdx.x * 256 + threadIdx.x;
    if (idx >= 2 * MTOT * DMOD) return;
    int dir = idx / (MTOT * DMOD);
    int rem = idx - dir * (MTOT * DMOD);
    int row = rem >> 7;
    int d = rem & (DMOD - 1);
    int b = row / LTOK;
    int tau = row - b * LTOK;
    int t = dir ? (LTOK - 1 - tau) : tau;
    int ld = l * 2 + dir;
    float c0 = cw[(ld * DMOD + d) * 2 + 0];
    float c1 = cw[(ld * DMOD + d) * 2 + 1];
    float x1 = xz[((size_t)(b * LTOK + t)) * 512 + dir * 256 + d];
    float acc = x1 * c1 + cb[ld * DMOD + d];
    if (tau > 0) {
        int tp = dir ? (t + 1) : (t - 1);
        acc += xz[((size_t)(b * LTOK + tp)) * 512 + dir * 256 + d] * c0;
    }
    acc = acc / (1.f + __expf(-acc));
    xc[(size_t)dir * MTOT * DMOD + rem] = acc;
}

// ---------------- chunked selective scan ----------------
__global__ __launch_bounds__(256) void scan_p1(
    const float* __restrict__ dbc, const float* __restrict__ xc,
    const float* __restrict__ A_log, float* __restrict__ sA, float* __restrict__ sH, int l)
{
    int n  = threadIdx.x & 15;
    int dl = threadIdx.x >> 4;
    int d  = blockIdx.x * 16 + dl;
    int b  = blockIdx.y;
    int z  = blockIdx.z;
    int dir = z >> 4;
    int c   = z & 15;
    int ld = l * 2 + dir;

    float a = -__expf(A_log[(ld * DMOD + d) * DST + n]);
    const float* dbcp = dbc + (size_t)dir * MTOT * 160 + (size_t)b * LTOK * 160;
    const float* xcp  = xc  + (size_t)dir * MTOT * DMOD + (size_t)b * LTOK * DMOD;

    int t0 = c * CLEN;
    int t1 = t0 + CLEN; if (t1 > LTOK) t1 = LTOK;

    float Aacc = 1.f, h = 0.f;
    for (int t = t0; t < t1; t++) {
        const float* row = dbcp + (size_t)t * 160;
        float delta = row[d];
        float Bv    = row[128 + n];
        float xcv   = xcp[(size_t)t * DMOD + d];
        float dA = __expf(delta * a);
        Aacc *= dA;
        h = fmaf(dA, h, delta * Bv * xcv);
    }
    size_t idx = (((size_t)(b * 2 + dir) * NCH + c) * DMOD + d) * DST + n;
    sA[idx] = Aacc;
    sH[idx] = h;
}

__global__ void scan_comb(const float* __restrict__ sA, const float* __restrict__ sH,
                          float* __restrict__ sS)
{
    int idx = blockIdx.x * 256 + threadIdx.x;
    if (idx >= BQ * 2 * DMOD * DST) return;
    int dn = idx & (DMOD * DST - 1);
    int bd = idx >> 11;
    size_t base = (size_t)bd * NCH * DMOD * DST + dn;
    float h = 0.f;
    #pragma unroll
    for (int c = 0; c < NCH; c++) {
        size_t p = base + (size_t)c * DMOD * DST;
        sS[p] = h;
        h = fmaf(sA[p], h, sH[p]);
    }
}

__global__ __launch_bounds__(256) void scan_p2(
    const float* __restrict__ dbc, const float* __restrict__ xc,
    const float* __restrict__ xz, const float* __restrict__ A_log,
    const float* __restrict__ Dpar, const float* __restrict__ sS,
    float* __restrict__ y, int l)
{
    int n  = threadIdx.x & 15;
    int dl = threadIdx.x >> 4;
    int d  = blockIdx.x * 16 + dl;
    int b  = blockIdx.y;
    int z  = blockIdx.z;
    int dir = z >> 4;
    int c   = z & 15;
    int ld = l * 2 + dir;

    float a  = -__expf(A_log[(ld * DMOD + d) * DST + n]);
    float Dp = Dpar[ld * DMOD + d];
    const float* dbcp = dbc + (size_t)dir * MTOT * 160 + (size_t)b * LTOK * 160;
    const float* xcp  = xc  + (size_t)dir * MTOT * DMOD + (size_t)b * LTOK * DMOD;
    const float* zp   = xz  + (size_t)b * LTOK * 512 + 128 + dir * 256;
    float*       yp   = y   + (size_t)b * LTOK * 256 + dir * 128;

    int t0 = c * CLEN;
    int t1 = t0 + CLEN; if (t1 > LTOK) t1 = LTOK;

    float h = sS[(((size_t)(b * 2 + dir) * NCH + c) * DMOD + d) * DST + n];
    for (int tau = t0; tau < t1; tau++) {
        const float* row = dbcp + (size_t)tau * 160;
        float delta = row[d];
        float Bv    = row[128 + n];
        float Cv    = row[144 + n];
        float xcv   = xcp[(size_t)tau * DMOD + d];
        float dA = __expf(delta * a);
        h = fmaf(dA, h, delta * Bv * xcv);
        float p = h * Cv;
        p += __shfl_xor_sync(0xffffffffu, p, 8);
        p += __shfl_xor_sync(0xffffffffu, p, 4);
        p += __shfl_xor_sync(0xffffffffu, p, 2);
        p += __shfl_xor_sync(0xffffffffu, p, 1);
        if (n == 0) {
            int t = dir ? (LTOK - 1 - tau) : tau;
            float zv = zp[(size_t)t * 512 + d];
            float sz = zv / (1.f + __expf(-zv));
            yp[(size_t)t * 256 + d] = (p + Dp * xcv) * sz;
        }
    }
}

// ---------------- layernorm over last dim (128) ----------------
__global__ void ln_k(const float* __restrict__ in, float* __restrict__ out,
                     const float* __restrict__ w, const float* __restrict__ b)
{
    int row = blockIdx.x;
    int t = threadIdx.x;
    float v = in[(size_t)row * DMOD + t];
    __shared__ float sm[4], sm2[4];
    float s = v;
    #pragma unroll
    for (int o = 16; o; o >>= 1) s += __shfl_xor_sync(0xffffffffu, s, o);
    if ((t & 31) == 0) sm[t >> 5] = s;
    __syncthreads();
    float mu = (sm[0] + sm[1] + sm[2] + sm[3]) * (1.f / 128.f);
    float dv = v - mu;
    float q = dv * dv;
    #pragma unroll
    for (int o = 16; o; o >>= 1) q += __shfl_xor_sync(0xffffffffu, q, o);
    if ((t & 31) == 0) sm2[t >> 5] = q;
    __syncthreads();
    float var = (sm2[0] + sm2[1] + sm2[2] + sm2[3]) * (1.f / 128.f);
    out[(size_t)row * DMOD + t] = dv * rsqrtf(var + 1e-5f) * w[t] + b[t];
}

// ---------------- final transposed write ----------------
__global__ void write_out(const float* __restrict__ P, float* __restrict__ out)
{
    int idx = blockIdx.x * 256 + threadIdx.x;
    if (idx >= BQ * PREDN * NVAR) return;
    int v = idx & (NVAR - 1);
    int p = (idx >> 10) % PREDN;
    int b = idx / (PREDN * NVAR);
    out[idx] = P[((size_t)(b * LTOK + v)) * PREDN + p];
}

// ---------------- launcher ----------------
extern "C" void kernel_launch(void* const* d_in, const int* in_sizes, int n_in,
                              void* d_out, int out_size)
{
    const float* x_enc     = (const float*)d_in[0];
    const float* x_mark    = (const float*)d_in[1];
    const float* emb_w     = (const float*)d_in[4];
    const float* emb_b     = (const float*)d_in[5];
    const float* in_proj_w = (const float*)d_in[6];
    const float* conv_w    = (const float*)d_in[7];
    const float* conv_b    = (const float*)d_in[8];
    const float* x_proj_w  = (const float*)d_in[9];
    const float* dt_proj_w = (const float*)d_in[10];
    const float* dt_proj_b = (const float*)d_in[11];
    const float* A_log     = (const float*)d_in[12];
    const float* D_param   = (const float*)d_in[13];
    const float* out_projw = (const float*)d_in[14];
    const float* norm1_w   = (const float*)d_in[15];
    const float* norm1_b   = (const float*)d_in[16];
    const float* norm2_w   = (const float*)d_in[17];
    const float* norm2_b   = (const float*)d_in[18];
    const float* ffn_w1    = (const float*)d_in[19];
    const float* ffn_b1    = (const float*)d_in[20];
    const float* ffn_w2    = (const float*)d_in[21];
    const float* ffn_b2    = (const float*)d_in[22];
    const float* fnorm_w   = (const float*)d_in[23];
    const float* fnorm_b   = (const float*)d_in[24];
    const float* proj_w    = (const float*)d_in[25];
    const float* proj_b    = (const float*)d_in[26];

    float *ptok, *ph, *pln1, *pffn, *pxz, *pxc, *pdbc, *py, *ppo, *pwxp, *pwop;
    float *psA, *psH, *psS;
    cudaGetSymbolAddress((void**)&ptok, g_tok);
    cudaGetSymbolAddress((void**)&ph,   g_h);
    cudaGetSymbolAddress((void**)&pln1, g_ln1);
    cudaGetSymbolAddress((void**)&pffn, g_ffn);
    cudaGetSymbolAddress((void**)&pxz,  g_xz);
    cudaGetSymbolAddress((void**)&pxc,  g_xc);
    cudaGetSymbolAddress((void**)&pdbc, g_dbc);
    cudaGetSymbolAddress((void**)&py,   g_y);
    cudaGetSymbolAddress((void**)&ppo,  g_po);
    cudaGetSymbolAddress((void**)&pwxp, g_wxp);
    cudaGetSymbolAddress((void**)&pwop, g_wop);
    cudaGetSymbolAddress((void**)&psA,  g_sA);
    cudaGetSymbolAddress((void**)&psH,  g_sH);
    cudaGetSymbolAddress((void**)&psS,  g_sS);

    const int MT = (MTOT + 127) / 128;   // 65

    // launch index 3 = in_proj GEMM of layer 0 (the one ncu captures)
    tok_prep<<<dim3(SEQ / 32, NVAR / 32, BQ), dim3(32, 8)>>>(x_enc, ptok);          // 0
    mark_prep<<<(BQ * TFEAT * SEQ + 255) / 256, 256>>>(x_mark, ptok);               // 1
    gemm_k<0><<<dim3(2, MT), 256>>>(ptok, emb_w, emb_b, nullptr, ph,                // 2
                                    MTOT, DMOD, SEQ, 0, 0, 0, 0);
    gemm_k<0><<<dim3(8, MT), 256>>>(ph, in_proj_w, nullptr, nullptr, pxz,           // 3 (profiled)
                                    MTOT, 512, DMOD, 0, 0, 0, 0);
    prep_wd<<<dim3(80, 4), 256>>>(x_proj_w, dt_proj_w, pwxp);
    prep_wop<<<(2 * DMOD * 256 + 255) / 256, 256>>>(out_projw, pwop);

    for (int l = 0; l < 2; l++) {
        if (l > 0)
            gemm_k<0><<<dim3(8, MT), 256>>>(ph, in_proj_w + (size_t)l * 2 * 256 * DMOD,
                                            nullptr, nullptr, pxz, MTOT, 512, DMOD, 0, 0, 0, 0);
        conv_silu<<<(2 * MTOT * DMOD + 255) / 256, 256>>>(pxz, conv_w, conv_b, pxc, l);
        gemm_k<3><<<dim3(3, MT, 2), 256>>>(pxc, pwxp + (size_t)l * 2 * 160 * DMOD,
                                           dt_proj_b + (size_t)l * 2 * DMOD, nullptr, pdbc,
                                           MTOT, 160, DMOD,
                                           (size_t)MTOT * DMOD, (size_t)160 * DMOD,
                                           (size_t)DMOD, (size_t)MTOT * 160);
        scan_p1<<<dim3(8, BQ, 32), 256>>>(pdbc, pxc, A_log, psA, psH, l);
        scan_comb<<<(BQ * 2 * DMOD * DST + 255) / 256, 256>>>(psA, psH, psS);
        scan_p2<<<dim3(8, BQ, 32), 256>>>(pdbc, pxc, pxz, A_log, D_param, psS, py, l);
        gemm_k<2><<<dim3(2, MT), 256>>>(py, pwop + (size_t)l * DMOD * 256,
                                        nullptr, ph, ph, MTOT, DMOD, 256, 0, 0, 0, 0);
        ln_k<<<MTOT, 128>>>(ph, pln1, norm1_w + l * DMOD, norm1_b + l * DMOD);
        gemm_k<1><<<dim3(2, MT), 256>>>(pln1, ffn_w1 + (size_t)l * DMOD * DMOD,
                                        ffn_b1 + l * DMOD, nullptr, pffn,
                                        MTOT, DMOD, DMOD, 0, 0, 0, 0);
        gemm_k<2><<<dim3(2, MT), 256>>>(pffn, ffn_w2 + (size_t)l * DMOD * DMOD,
                                        ffn_b2 + l * DMOD, pln1, ph, MTOT, DMOD, DMOD, 0, 0, 0, 0);
        ln_k<<<MTOT, 128>>>(ph, ph, norm2_w + l * DMOD, norm2_b + l * DMOD);
    }

    ln_k<<<MTOT, 128>>>(ph, pln1, fnorm_w, fnorm_b);
    gemm_k<0><<<dim3(2, MT), 256>>>(pln1, proj_w, proj_b, nullptr, ppo,
                                    MTOT, PREDN, DMOD, 0, 0, 0, 0);
    write_out<<<(BQ * PREDN * NVAR + 255) / 256, 256>>>(ppo, (float*)d_out);
}

// round 6
// speedup vs baseline: 3.9317x; 1.2737x over previous
#include <cuda_runtime.h>
#include <math.h>

#define BQ    8
#define SEQ   512
#define NVAR  1024
#define TFEAT 7
#define LTOK  1031           // NVAR + TFEAT
#define MTOT  8248           // BQ * LTOK
#define DMOD  128
#define DST   16
#define PREDN 96
#define NCH   32
#define CLEN  33             // ceil(LTOK/NCH)

// ---------------- scratch (device globals; no allocation allowed) ----------------
__device__ float g_tok[MTOT * SEQ];
__device__ float g_h  [MTOT * DMOD];
__device__ float g_ln1[MTOT * DMOD];
__device__ float g_ffn[MTOT * DMOD];
__device__ float g_xz [MTOT * 512];
__device__ float g_xc [2 * MTOT * DMOD];
__device__ float g_dbc[2 * MTOT * 160];
__device__ float g_y  [MTOT * 256];
__device__ float g_po [MTOT * PREDN];
__device__ float g_wxp[4 * 160 * DMOD];
__device__ float g_wop[2 * DMOD * 256];
__device__ float g_sA [BQ * 2 * NCH * DMOD * DST];
__device__ float g_sH [BQ * 2 * NCH * DMOD * DST];
__device__ float g_sS [BQ * 2 * NCH * DMOD * DST];

// ---------------- token transpose + mask ----------------
__global__ void tok_prep(const float* __restrict__ x_enc, float* __restrict__ tok)
{
    __shared__ float tile[32][33];
    int b = blockIdx.z;
    int s0 = blockIdx.x * 32, v0 = blockIdx.y * 32;
    #pragma unroll
    for (int i = 0; i < 4; i++) {
        int s = s0 + threadIdx.y + i * 8;
        float x = x_enc[((size_t)(b * SEQ + s)) * NVAR + v0 + threadIdx.x];
        tile[threadIdx.y + i * 8][threadIdx.x] = (x == -9999.0f) ? -1.0f : x;
    }
    __syncthreads();
    #pragma unroll
    for (int i = 0; i < 4; i++) {
        int v = v0 + threadIdx.y + i * 8;
        tok[((size_t)(b * LTOK + v)) * SEQ + s0 + threadIdx.x] = tile[threadIdx.x][threadIdx.y + i * 8];
    }
}

__global__ void mark_prep(const float* __restrict__ x_mark, float* __restrict__ tok)
{
    int idx = blockIdx.x * 256 + threadIdx.x;
    if (idx >= BQ * TFEAT * SEQ) return;
    int s = idx & (SEQ - 1);
    int r = idx >> 9;
    int f = r % TFEAT;
    int b = r / TFEAT;
    tok[((size_t)(b * LTOK + NVAR + f)) * SEQ + s] = x_mark[((size_t)(b * SEQ + s)) * TFEAT + f];
}

// ---------------- combined x_proj/dt_proj weight prep ----------------
__global__ void prep_wd(const float* __restrict__ xpw, const float* __restrict__ dpw,
                        float* __restrict__ out)
{
    int ld = blockIdx.y;
    int idx = blockIdx.x * 256 + threadIdx.x;
    if (idx >= 160 * DMOD) return;
    int i = idx / DMOD, j = idx - i * DMOD;
    const float* xp = xpw + ld * 40 * DMOD;
    float v;
    if (i < DMOD) {
        const float* dp = dpw + (ld * DMOD + i) * 8;
        v = 0.f;
        #pragma unroll
        for (int r = 0; r < 8; r++) v += dp[r] * xp[r * DMOD + j];
    } else {
        v = xp[(8 + (i - DMOD)) * DMOD + j];
    }
    out[ld * 160 * DMOD + idx] = v;
}

// ---------------- out_proj weight concat ----------------
__global__ void prep_wop(const float* __restrict__ opw, float* __restrict__ out)
{
    int idx = blockIdx.x * 256 + threadIdx.x;
    if (idx >= 2 * DMOD * 256) return;
    int l = idx / (DMOD * 256);
    int r = idx - l * DMOD * 256;
    int n = r >> 8;
    int k = r & 255;
    int dir = k >> 7;
    int kk = k & 127;
    out[idx] = opw[(((size_t)(l * 2 + dir) * DMOD) + n) * DMOD + kk];
}

// ---------------- fp32 GEMM: C[M,N] = A[M,K] @ W[N,K]^T (+epilogue) --------------
// BM=128, BN=64, BK=16, 256 threads, warp grid 4x2 (32x32 warp tile), 8x4/thread.
template<int EPI>
__global__ __launch_bounds__(256) void gemm_k(
    const float* __restrict__ A, const float* __restrict__ W,
    const float* __restrict__ bias, const float* __restrict__ resid,
    float* __restrict__ C, int M, int N, int K,
    size_t sA, size_t sW, size_t sB, size_t sC)
{
    if (gridDim.z > 1) {
        A += (size_t)blockIdx.z * sA;
        W += (size_t)blockIdx.z * sW;
        C += (size_t)blockIdx.z * sC;
        if (bias)  bias  += (size_t)blockIdx.z * sB;
        if (resid) resid += (size_t)blockIdx.z * sC;
    }
    __shared__ float As[2][16][128];
    __shared__ float Bs[2][16][64];
    int bm = blockIdx.y * 128;
    int bn = blockIdx.x * 64;
    int tid = threadIdx.x;

    int wid = tid >> 5, lane = tid & 31;
    int warp_m = wid >> 1, warp_n = wid & 1;
    int lm = lane >> 3, ln = lane & 7;
    int mb  = warp_m * 32 + lm * 8;
    int nbs = warp_n * 32 + ln * 4;

    int ar = tid >> 1;
    int ac = (tid & 1) * 8;
    bool aact = (bm + ar < M);
    const float* Ap = A + (size_t)(bm + ar) * K + ac;

    int br = tid >> 2;
    int bc = (tid & 3) * 4;
    bool wact = (bn + br < N);
    const float* Wp = W + (size_t)(bn + br) * K + bc;

    float acc[8][4] = {};
    float4 ra0 = make_float4(0,0,0,0), ra1 = make_float4(0,0,0,0), rw = make_float4(0,0,0,0);

    if (aact) { ra0 = *(const float4*)(Ap); ra1 = *(const float4*)(Ap + 4); }
    if (wact) { rw = *(const float4*)(Wp); }
    {
        float* as = &As[0][ac][ar];
        as[0*128] = ra0.x; as[1*128] = ra0.y; as[2*128] = ra0.z; as[3*128] = ra0.w;
        as[4*128] = ra1.x; as[5*128] = ra1.y; as[6*128] = ra1.z; as[7*128] = ra1.w;
        float* bs = &Bs[0][bc][br];
        bs[0*64] = rw.x; bs[1*64] = rw.y; bs[2*64] = rw.z; bs[3*64] = rw.w;
    }
    __syncthreads();

    int NT = K >> 4;
    for (int t = 0; t < NT; t++) {
        int buf = t & 1;
        if (t + 1 < NT) {
            int k0 = (t + 1) << 4;
            if (aact) { ra0 = *(const float4*)(Ap + k0); ra1 = *(const float4*)(Ap + k0 + 4); }
            if (wact) { rw = *(const float4*)(Wp + k0); }
        }
        #pragma unroll
        for (int k = 0; k < 16; k++) {
            float4 a0 = *(const float4*)&As[buf][k][mb];
            float4 a1 = *(const float4*)&As[buf][k][mb + 4];
            float4 b0 = *(const float4*)&Bs[buf][k][nbs];
            float av[8] = {a0.x, a0.y, a0.z, a0.w, a1.x, a1.y, a1.z, a1.w};
            float bv[4] = {b0.x, b0.y, b0.z, b0.w};
            #pragma unroll
            for (int i = 0; i < 8; i++)
                #pragma unroll
                for (int j = 0; j < 4; j++)
                    acc[i][j] = fmaf(av[i], bv[j], acc[i][j]);
        }
        if (t + 1 < NT) {
            int nb = buf ^ 1;
            float* as = &As[nb][ac][ar];
            as[0*128] = ra0.x; as[1*128] = ra0.y; as[2*128] = ra0.z; as[3*128] = ra0.w;
            as[4*128] = ra1.x; as[5*128] = ra1.y; as[6*128] = ra1.z; as[7*128] = ra1.w;
            float* bs = &Bs[nb][bc][br];
            bs[0*64] = rw.x; bs[1*64] = rw.y; bs[2*64] = rw.z; bs[3*64] = rw.w;
            __syncthreads();
        }
    }

    #pragma unroll
    for (int i = 0; i < 8; i++) {
        int m = bm + mb + i;
        if (m >= M) continue;
        #pragma unroll
        for (int j = 0; j < 4; j++) {
            int n = bn + nbs + j;
            if (n >= N) continue;
            float v = acc[i][j];
            if (EPI == 0) {
                if (bias) v += bias[n];
            } else if (EPI == 1) {
                v = fmaxf(v + bias[n], 0.f);
            } else if (EPI == 2) {
                if (bias) v += bias[n];
                v += resid[(size_t)m * N + n];
            } else if (EPI == 3) {
                if (n < DMOD) {
                    v += bias[n];
                    v = (v > 20.f) ? v : log1pf(__expf(v));
                }
            }
            C[(size_t)m * N + n] = v;
        }
    }
}

// ---------------- depthwise causal conv (DCONV=2) + silu ----------------
__global__ void conv_silu(const float* __restrict__ xz, const float* __restrict__ cw,
                          const float* __restrict__ cb, float* __restrict__ xc, int l)
{
    int idx = blockIdx.x * 256 + threadIdx.x;
    if (idx >= 2 * MTOT * DMOD) return;
    int dir = idx / (MTOT * DMOD);
    int rem = idx - dir * (MTOT * DMOD);
    int row = rem >> 7;
    int d = rem & (DMOD - 1);
    int b = row / LTOK;
    int tau = row - b * LTOK;
    int t = dir ? (LTOK - 1 - tau) : tau;
    int ld = l * 2 + dir;
    float c0 = cw[(ld * DMOD + d) * 2 + 0];
    float c1 = cw[(ld * DMOD + d) * 2 + 1];
    float x1 = xz[((size_t)(b * LTOK + t)) * 512 + dir * 256 + d];
    float acc = x1 * c1 + cb[ld * DMOD + d];
    if (tau > 0) {
        int tp = dir ? (t + 1) : (t - 1);
        acc += xz[((size_t)(b * LTOK + tp)) * 512 + dir * 256 + d] * c0;
    }
    acc = acc / (1.f + __expf(-acc));
    xc[(size_t)dir * MTOT * DMOD + rem] = acc;
}

// ---------------- chunked selective scan (thread = d, 16 states in regs) ---------
// pass1: per-chunk local scan; store prod(dA) and local end h
__global__ __launch_bounds__(128) void scan_p1(
    const float* __restrict__ dbc, const float* __restrict__ xc,
    const float* __restrict__ A_log, float* __restrict__ sA, float* __restrict__ sH, int l)
{
    int d  = threadIdx.x;
    int c  = blockIdx.x;
    int b  = blockIdx.y;
    int dir = blockIdx.z;
    int ld = l * 2 + dir;

    float a[DST];
    {
        const float* Ab = A_log + ((size_t)(ld * DMOD + d)) * DST;
        #pragma unroll
        for (int q = 0; q < 4; q++) {
            float4 v = *(const float4*)(Ab + q * 4);
            a[q*4+0] = -__expf(v.x); a[q*4+1] = -__expf(v.y);
            a[q*4+2] = -__expf(v.z); a[q*4+3] = -__expf(v.w);
        }
    }
    const float* dbcp = dbc + (size_t)dir * MTOT * 160 + (size_t)b * LTOK * 160;
    const float* xcp  = xc  + (size_t)dir * MTOT * DMOD + (size_t)b * LTOK * DMOD;

    int t0 = c * CLEN;
    int t1 = t0 + CLEN; if (t1 > LTOK) t1 = LTOK;

    float Aacc[DST], h[DST];
    #pragma unroll
    for (int n = 0; n < DST; n++) { Aacc[n] = 1.f; h[n] = 0.f; }

    for (int t = t0; t < t1; t++) {
        const float* row = dbcp + (size_t)t * 160;
        float delta = row[d];
        float xcv   = xcp[(size_t)t * DMOD + d];
        float dbx   = delta * xcv;
        float Bv[DST];
        #pragma unroll
        for (int q = 0; q < 4; q++) {
            float4 v = *(const float4*)(row + 128 + q * 4);
            Bv[q*4+0] = v.x; Bv[q*4+1] = v.y; Bv[q*4+2] = v.z; Bv[q*4+3] = v.w;
        }
        #pragma unroll
        for (int n = 0; n < DST; n++) {
            float dA = __expf(delta * a[n]);
            Aacc[n] *= dA;
            h[n] = fmaf(dA, h[n], dbx * Bv[n]);
        }
    }
    size_t base = (((size_t)(b * 2 + dir) * NCH + c) * DMOD + d) * DST;
    #pragma unroll
    for (int q = 0; q < 4; q++) {
        *(float4*)(sA + base + q * 4) = make_float4(Aacc[q*4], Aacc[q*4+1], Aacc[q*4+2], Aacc[q*4+3]);
        *(float4*)(sH + base + q * 4) = make_float4(h[q*4], h[q*4+1], h[q*4+2], h[q*4+3]);
    }
}

// combine: sequential over chunks, store true start state per chunk
__global__ void scan_comb(const float* __restrict__ sA, const float* __restrict__ sH,
                          float* __restrict__ sS)
{
    int idx = blockIdx.x * 256 + threadIdx.x;
    if (idx >= BQ * 2 * DMOD * DST) return;
    int dn = idx & (DMOD * DST - 1);
    int bd = idx >> 11;
    size_t base = (size_t)bd * NCH * DMOD * DST + dn;
    float h = 0.f;
    #pragma unroll
    for (int c = 0; c < NCH; c++) {
        size_t p = base + (size_t)c * DMOD * DST;
        sS[p] = h;
        h = fmaf(sA[p], h, sH[p]);
    }
}

// pass2: re-scan chunk from true start state, write gated y
__global__ __launch_bounds__(128) void scan_p2(
    const float* __restrict__ dbc, const float* __restrict__ xc,
    const float* __restrict__ xz, const float* __restrict__ A_log,
    const float* __restrict__ Dpar, const float* __restrict__ sS,
    float* __restrict__ y, int l)
{
    int d  = threadIdx.x;
    int c  = blockIdx.x;
    int b  = blockIdx.y;
    int dir = blockIdx.z;
    int ld = l * 2 + dir;

    float a[DST];
    {
        const float* Ab = A_log + ((size_t)(ld * DMOD + d)) * DST;
        #pragma unroll
        for (int q = 0; q < 4; q++) {
            float4 v = *(const float4*)(Ab + q * 4);
            a[q*4+0] = -__expf(v.x); a[q*4+1] = -__expf(v.y);
            a[q*4+2] = -__expf(v.z); a[q*4+3] = -__expf(v.w);
        }
    }
    float Dp = Dpar[ld * DMOD + d];
    const float* dbcp = dbc + (size_t)dir * MTOT * 160 + (size_t)b * LTOK * 160;
    const float* xcp  = xc  + (size_t)dir * MTOT * DMOD + (size_t)b * LTOK * DMOD;
    const float* zp   = xz  + (size_t)b * LTOK * 512 + 128 + dir * 256;
    float*       yp   = y   + (size_t)b * LTOK * 256 + dir * 128;

    int t0 = c * CLEN;
    int t1 = t0 + CLEN; if (t1 > LTOK) t1 = LTOK;

    float h[DST];
    {
        size_t base = (((size_t)(b * 2 + dir) * NCH + c) * DMOD + d) * DST;
        #pragma unroll
        for (int q = 0; q < 4; q++) {
            float4 v = *(const float4*)(sS + base + q * 4);
            h[q*4+0] = v.x; h[q*4+1] = v.y; h[q*4+2] = v.z; h[q*4+3] = v.w;
        }
    }

    for (int tau = t0; tau < t1; tau++) {
        const float* row = dbcp + (size_t)tau * 160;
        float delta = row[d];
        float xcv   = xcp[(size_t)tau * DMOD + d];
        float dbx   = delta * xcv;
        float Bv[DST], Cv[DST];
        #pragma unroll
        for (int q = 0; q < 4; q++) {
            float4 v = *(const float4*)(row + 128 + q * 4);
            Bv[q*4+0] = v.x; Bv[q*4+1] = v.y; Bv[q*4+2] = v.z; Bv[q*4+3] = v.w;
            float4 u = *(const float4*)(row + 144 + q * 4);
            Cv[q*4+0] = u.x; Cv[q*4+1] = u.y; Cv[q*4+2] = u.z; Cv[q*4+3] = u.w;
        }
        float acc = 0.f;
        #pragma unroll
        for (int n = 0; n < DST; n++) {
            float dA = __expf(delta * a[n]);
            h[n] = fmaf(dA, h[n], dbx * Bv[n]);
            acc = fmaf(h[n], Cv[n], acc);
        }
        int t = dir ? (LTOK - 1 - tau) : tau;
        float zv = zp[(size_t)t * 512 + d];
        float sz = zv / (1.f + __expf(-zv));
        yp[(size_t)t * 256 + d] = (acc + Dp * xcv) * sz;
    }
}

// ---------------- layernorm: warp per row, 8 rows/block ----------------
__global__ __launch_bounds__(256) void ln_k(const float* __restrict__ in, float* __restrict__ out,
                                            const float* __restrict__ w, const float* __restrict__ b)
{
    int warp = threadIdx.x >> 5, lane = threadIdx.x & 31;
    int row = blockIdx.x * 8 + warp;
    const float4 v4 = *(const float4*)(in + (size_t)row * DMOD + lane * 4);
    float s = v4.x + v4.y + v4.z + v4.w;
    #pragma unroll
    for (int o = 16; o; o >>= 1) s += __shfl_xor_sync(0xffffffffu, s, o);
    float mu = s * (1.f / 128.f);
    float dx = v4.x - mu, dy = v4.y - mu, dz = v4.z - mu, dw = v4.w - mu;
    float q = dx*dx + dy*dy + dz*dz + dw*dw;
    #pragma unroll
    for (int o = 16; o; o >>= 1) q += __shfl_xor_sync(0xffffffffu, q, o);
    float rs = rsqrtf(q * (1.f / 128.f) + 1e-5f);
    float4 w4 = *(const float4*)(w + lane * 4);
    float4 b4 = *(const float4*)(b + lane * 4);
    float4 o4;
    o4.x = dx * rs * w4.x + b4.x;
    o4.y = dy * rs * w4.y + b4.y;
    o4.z = dz * rs * w4.z + b4.z;
    o4.w = dw * rs * w4.w + b4.w;
    *(float4*)(out + (size_t)row * DMOD + lane * 4) = o4;
}

// ---------------- final transposed write ----------------
__global__ void write_out(const float* __restrict__ P, float* __restrict__ out)
{
    int idx = blockIdx.x * 256 + threadIdx.x;
    if (idx >= BQ * PREDN * NVAR) return;
    int v = idx & (NVAR - 1);
    int p = (idx >> 10) % PREDN;
    int b = idx / (PREDN * NVAR);
    out[idx] = P[((size_t)(b * LTOK + v)) * PREDN + p];
}

// ---------------- launcher ----------------
extern "C" void kernel_launch(void* const* d_in, const int* in_sizes, int n_in,
                              void* d_out, int out_size)
{
    const float* x_enc     = (const float*)d_in[0];
    const float* x_mark    = (const float*)d_in[1];
    const float* emb_w     = (const float*)d_in[4];
    const float* emb_b     = (const float*)d_in[5];
    const float* in_proj_w = (const float*)d_in[6];
    const float* conv_w    = (const float*)d_in[7];
    const float* conv_b    = (const float*)d_in[8];
    const float* x_proj_w  = (const float*)d_in[9];
    const float* dt_proj_w = (const float*)d_in[10];
    const float* dt_proj_b = (const float*)d_in[11];
    const float* A_log     = (const float*)d_in[12];
    const float* D_param   = (const float*)d_in[13];
    const float* out_projw = (const float*)d_in[14];
    const float* norm1_w   = (const float*)d_in[15];
    const float* norm1_b   = (const float*)d_in[16];
    const float* norm2_w   = (const float*)d_in[17];
    const float* norm2_b   = (const float*)d_in[18];
    const float* ffn_w1    = (const float*)d_in[19];
    const float* ffn_b1    = (const float*)d_in[20];
    const float* ffn_w2    = (const float*)d_in[21];
    const float* ffn_b2    = (const float*)d_in[22];
    const float* fnorm_w   = (const float*)d_in[23];
    const float* fnorm_b   = (const float*)d_in[24];
    const float* proj_w    = (const float*)d_in[25];
    const float* proj_b    = (const float*)d_in[26];

    float *ptok, *ph, *pln1, *pffn, *pxz, *pxc, *pdbc, *py, *ppo, *pwxp, *pwop;
    float *psA, *psH, *psS;
    cudaGetSymbolAddress((void**)&ptok, g_tok);
    cudaGetSymbolAddress((void**)&ph,   g_h);
    cudaGetSymbolAddress((void**)&pln1, g_ln1);
    cudaGetSymbolAddress((void**)&pffn, g_ffn);
    cudaGetSymbolAddress((void**)&pxz,  g_xz);
    cudaGetSymbolAddress((void**)&pxc,  g_xc);
    cudaGetSymbolAddress((void**)&pdbc, g_dbc);
    cudaGetSymbolAddress((void**)&py,   g_y);
    cudaGetSymbolAddress((void**)&ppo,  g_po);
    cudaGetSymbolAddress((void**)&pwxp, g_wxp);
    cudaGetSymbolAddress((void**)&pwop, g_wop);
    cudaGetSymbolAddress((void**)&psA,  g_sA);
    cudaGetSymbolAddress((void**)&psH,  g_sH);
    cudaGetSymbolAddress((void**)&psS,  g_sS);

    const int MT = (MTOT + 127) / 128;   // 65

    // launch index 3 = in_proj GEMM of layer 0 (the one ncu captures)
    tok_prep<<<dim3(SEQ / 32, NVAR / 32, BQ), dim3(32, 8)>>>(x_enc, ptok);          // 0
    mark_prep<<<(BQ * TFEAT * SEQ + 255) / 256, 256>>>(x_mark, ptok);               // 1
    gemm_k<0><<<dim3(2, MT), 256>>>(ptok, emb_w, emb_b, nullptr, ph,                // 2
                                    MTOT, DMOD, SEQ, 0, 0, 0, 0);
    gemm_k<0><<<dim3(8, MT), 256>>>(ph, in_proj_w, nullptr, nullptr, pxz,           // 3 (profiled)
                                    MTOT, 512, DMOD, 0, 0, 0, 0);
    prep_wd<<<dim3(80, 4), 256>>>(x_proj_w, dt_proj_w, pwxp);
    prep_wop<<<(2 * DMOD * 256 + 255) / 256, 256>>>(out_projw, pwop);

    for (int l = 0; l < 2; l++) {
        if (l > 0)
            gemm_k<0><<<dim3(8, MT), 256>>>(ph, in_proj_w + (size_t)l * 2 * 256 * DMOD,
                                            nullptr, nullptr, pxz, MTOT, 512, DMOD, 0, 0, 0, 0);
        conv_silu<<<(2 * MTOT * DMOD + 255) / 256, 256>>>(pxz, conv_w, conv_b, pxc, l);
        gemm_k<3><<<dim3(3, MT, 2), 256>>>(pxc, pwxp + (size_t)l * 2 * 160 * DMOD,
                                           dt_proj_b + (size_t)l * 2 * DMOD, nullptr, pdbc,
                                           MTOT, 160, DMOD,
                                           (size_t)MTOT * DMOD, (size_t)160 * DMOD,
                                           (size_t)DMOD, (size_t)MTOT * 160);
        scan_p1<<<dim3(NCH, BQ, 2), 128>>>(pdbc, pxc, A_log, psA, psH, l);
        scan_comb<<<(BQ * 2 * DMOD * DST + 255) / 256, 256>>>(psA, psH, psS);
        scan_p2<<<dim3(NCH, BQ, 2), 128>>>(pdbc, pxc, pxz, A_log, D_param, psS, py, l);
        gemm_k<2><<<dim3(2, MT), 256>>>(py, pwop + (size_t)l * DMOD * 256,
                                        nullptr, ph, ph, MTOT, DMOD, 256, 0, 0, 0, 0);
        ln_k<<<MTOT / 8, 256>>>(ph, pln1, norm1_w + l * DMOD, norm1_b + l * DMOD);
        gemm_k<1><<<dim3(2, MT), 256>>>(pln1, ffn_w1 + (size_t)l * DMOD * DMOD,
                                        ffn_b1 + l * DMOD, nullptr, pffn,
                                        MTOT, DMOD, DMOD, 0, 0, 0, 0);
        gemm_k<2><<<dim3(2, MT), 256>>>(pffn, ffn_w2 + (size_t)l * DMOD * DMOD,
                                        ffn_b2 + l * DMOD, pln1, ph, MTOT, DMOD, DMOD, 0, 0, 0, 0);
        ln_k<<<MTOT / 8, 256>>>(ph, ph, norm2_w + l * DMOD, norm2_b + l * DMOD);
    }

    ln_k<<<MTOT / 8, 256>>>(ph, pln1, fnorm_w, fnorm_b);
    gemm_k<0><<<dim3(2, MT), 256>>>(pln1, proj_w, proj_b, nullptr, ppo,
                                    MTOT, PREDN, DMOD, 0, 0, 0, 0);
    write_out<<<(BQ * PREDN * NVAR + 255) / 256, 256>>>(ppo, (float*)d_out);
}